// round 1
// baseline (speedup 1.0000x reference)
#include <cuda_runtime.h>
#include <cstdint>

// ---------------- scratch (device globals; no allocation in kernel_launch) ----------------
// y_raw layout: [k=768][pos=32768], pos = b*16384 + d*1024 + h*32 + w
__device__ float g_yraw[768 * 32768];   // ~100.7 MB
__device__ float g_mu[32768];
__device__ float g_rstd[32768];
__device__ float g_wg[768 * 192];       // gamma[k] * W[k][n]
__device__ float g_s1[192];             // sum_k gamma[k]*W[k][n]
__device__ float g_s2[192];             // sum_k beta[k]*W[k][n]

// ---------------- kernel 1: gather/scatter x -> y_raw ----------------
// x: (2, 96, 32, 64, 64) fp32. Each thread handles one float2 (two adjacent W elems).
__global__ void k_scatter(const float* __restrict__ x) {
    int t = blockIdx.x * blockDim.x + threadIdx.x;   // 12,582,912 threads
    if (t >= 12582912) return;
    float2 v = reinterpret_cast<const float2*>(x)[t];
    int w2  = t & 31;          // output w (0..31)
    int tmp = t >> 5;
    int yy  = tmp & 63; tmp >>= 6;   // input H index
    int z   = tmp & 31; tmp >>= 5;   // input D index
    int c   = tmp % 96;
    int b   = tmp / 96;
    int p0  = ((z & 1) << 2) | ((yy & 1) << 1);      // ww bit added below
    int pos = b * 16384 + (z >> 1) * 1024 + (yy >> 1) * 32 + w2;
    g_yraw[(p0 * 96 + c) * 32768 + pos]       = v.x;  // ww=0
    g_yraw[((p0 + 1) * 96 + c) * 32768 + pos] = v.y;  // ww=1
}

// ---------------- kernel 2: per-position mean / rstd ----------------
// block = 256 threads = 64 positions x 4 k-chunks of 192 rows
__global__ void k_stats() {
    __shared__ float ssum[256];
    __shared__ float ssq[256];
    int posLocal = threadIdx.x & 63;
    int kc       = threadIdx.x >> 6;  // 0..3
    int pos      = blockIdx.x * 64 + posLocal;
    const float* base = g_yraw + (size_t)kc * 192 * 32768 + pos;
    float s = 0.f, q = 0.f;
#pragma unroll 8
    for (int r = 0; r < 192; r++) {
        float v = base[(size_t)r * 32768];
        s += v;
        q += v * v;
    }
    ssum[threadIdx.x] = s;
    ssq[threadIdx.x]  = q;
    __syncthreads();
    if (threadIdx.x < 64) {
        float S = ssum[threadIdx.x] + ssum[threadIdx.x + 64] + ssum[threadIdx.x + 128] + ssum[threadIdx.x + 192];
        float Q = ssq[threadIdx.x]  + ssq[threadIdx.x + 64]  + ssq[threadIdx.x + 128]  + ssq[threadIdx.x + 192];
        int p = blockIdx.x * 64 + threadIdx.x;
        float mu  = S * (1.0f / 768.0f);
        float var = Q * (1.0f / 768.0f) - mu * mu;
        g_mu[p]   = mu;
        g_rstd[p] = rsqrtf(var + 1e-5f);
    }
}

// ---------------- kernel 3a: wg = gamma[k] * W ----------------
__global__ void k_wg(const float* __restrict__ gamma, const float* __restrict__ w) {
    int i = blockIdx.x * 256 + threadIdx.x;
    if (i < 768 * 192) g_wg[i] = gamma[i / 192] * w[i];
}

// ---------------- kernel 3b: s1[n] = sum gamma*W, s2[n] = sum beta*W ----------------
__global__ void k_s12(const float* __restrict__ gamma, const float* __restrict__ beta,
                      const float* __restrict__ w) {
    int n = blockIdx.x;
    __shared__ float s1s[256];
    __shared__ float s2s[256];
    float s1 = 0.f, s2 = 0.f;
    for (int k = threadIdx.x; k < 768; k += 256) {
        float wv = w[k * 192 + n];
        s1 += gamma[k] * wv;
        s2 += beta[k] * wv;
    }
    s1s[threadIdx.x] = s1;
    s2s[threadIdx.x] = s2;
    __syncthreads();
    for (int off = 128; off > 0; off >>= 1) {
        if (threadIdx.x < off) {
            s1s[threadIdx.x] += s1s[threadIdx.x + off];
            s2s[threadIdx.x] += s2s[threadIdx.x + off];
        }
        __syncthreads();
    }
    if (threadIdx.x == 0) { g_s1[n] = s1s[0]; g_s2[n] = s2s[0]; }
}

// ---------------- kernel 4: fused GEMM + LayerNorm epilogue + transpose writeback ----------
__device__ __forceinline__ unsigned long long ffma2(unsigned long long a,
                                                    unsigned long long b,
                                                    unsigned long long c) {
    unsigned long long d;
    asm("fma.rn.f32x2 %0, %1, %2, %3;" : "=l"(d) : "l"(a), "l"(b), "l"(c));
    return d;
}

// Tile: 256 M x 64 N, KT=16, 256 threads, micro-tile 8M x 8N (packed pairs along M)
__global__ void __launch_bounds__(256, 2) k_gemm(float* __restrict__ out) {
    __shared__ float  As[2][16][256];   // 32 KB
    __shared__ float2 Bs[2][16][64];    // 16 KB (values duplicated (v,v), permuted layout)

    const int m0  = blockIdx.x * 256;
    const int n0  = blockIdx.y * 64;
    const int tid = threadIdx.x;
    const int tx  = tid & 7;    // n-group (8 n each)
    const int ty  = tid >> 3;   // m-group (8 m each, 0..31)

    unsigned long long acc[4][8];
#pragma unroll
    for (int pi = 0; pi < 4; pi++)
#pragma unroll
        for (int j = 0; j < 8; j++) acc[pi][j] = 0ULL;

    // gmem->smem load mapping
    const int aRow = tid >> 6;            // 0..3 (strided by 4 -> 16 rows)
    const int aCol = (tid & 63) << 2;     // float4 column
    const int bRow = tid >> 6;            // 0..3
    const int bCol = tid & 63;            // n index within tile
    const int bPerm = ((bCol & 7) << 3) | (bCol >> 3);  // so compute reads [j*8+tx] conflict-free

    float4 aPf[4];
    float  bPf[4];

    // prefetch tile 0
#pragma unroll
    for (int r = 0; r < 4; r++)
        aPf[r] = *reinterpret_cast<const float4*>(&g_yraw[(size_t)(aRow + r * 4) * 32768 + m0 + aCol]);
#pragma unroll
    for (int r = 0; r < 4; r++)
        bPf[r] = g_wg[(bRow + r * 4) * 192 + n0 + bCol];
#pragma unroll
    for (int r = 0; r < 4; r++)
        *reinterpret_cast<float4*>(&As[0][aRow + r * 4][aCol]) = aPf[r];
#pragma unroll
    for (int r = 0; r < 4; r++)
        Bs[0][bRow + r * 4][bPerm] = make_float2(bPf[r], bPf[r]);
    __syncthreads();

    const int NT = 48;   // 768 / 16
    for (int t = 0; t < NT; t++) {
        int cur = t & 1;
        if (t < NT - 1) {
            int k0 = (t + 1) * 16;
#pragma unroll
            for (int r = 0; r < 4; r++)
                aPf[r] = *reinterpret_cast<const float4*>(&g_yraw[(size_t)(k0 + aRow + r * 4) * 32768 + m0 + aCol]);
#pragma unroll
            for (int r = 0; r < 4; r++)
                bPf[r] = g_wg[(k0 + bRow + r * 4) * 192 + n0 + bCol];
        }
#pragma unroll
        for (int kk = 0; kk < 16; kk++) {
            unsigned long long a2[4], b2[8];
#pragma unroll
            for (int pi = 0; pi < 4; pi++)
                a2[pi] = *reinterpret_cast<const unsigned long long*>(&As[cur][kk][ty * 8 + pi * 2]);
#pragma unroll
            for (int j = 0; j < 8; j++)
                b2[j] = *reinterpret_cast<const unsigned long long*>(&Bs[cur][kk][j * 8 + tx]);
#pragma unroll
            for (int pi = 0; pi < 4; pi++)
#pragma unroll
                for (int j = 0; j < 8; j++)
                    acc[pi][j] = ffma2(a2[pi], b2[j], acc[pi][j]);
        }
        if (t < NT - 1) {
            __syncthreads();
            int nxt = cur ^ 1;
#pragma unroll
            for (int r = 0; r < 4; r++)
                *reinterpret_cast<float4*>(&As[nxt][aRow + r * 4][aCol]) = aPf[r];
#pragma unroll
            for (int r = 0; r < 4; r++)
                Bs[nxt][bRow + r * 4][bPerm] = make_float2(bPf[r], bPf[r]);
            __syncthreads();
        }
    }

    // ---- fused LayerNorm epilogue ----
    // out = rstd*dot + (-rstd*mu)*s1[n] + s2[n]
    float alpha[8], betaM[8], s1v[8], s2v[8];
#pragma unroll
    for (int i = 0; i < 8; i++) {
        int m = m0 + ty * 8 + i;
        float rs = g_rstd[m];
        alpha[i] = rs;
        betaM[i] = -rs * g_mu[m];
    }
#pragma unroll
    for (int j = 0; j < 8; j++) {
        int n = n0 + tx * 8 + j;
        s1v[j] = g_s1[n];
        s2v[j] = g_s2[n];
    }

    // stage through smem for coalesced channel-major writeback (4 chunks of 16 n)
    float* so = &As[0][0][0];   // reuse 16*256 floats
    for (int c = 0; c < 4; c++) {
        __syncthreads();
        if ((tx >> 1) == c) {
            int nl0 = (tx & 1) * 8;
#pragma unroll
            for (int pi = 0; pi < 4; pi++) {
#pragma unroll
                for (int j = 0; j < 8; j++) {
                    unsigned long long av = acc[pi][j];
                    float ax = __uint_as_float((unsigned)(av & 0xffffffffu));
                    float ay = __uint_as_float((unsigned)(av >> 32));
                    int mi = pi * 2;
                    float v0 = fmaf(alpha[mi],     ax, fmaf(betaM[mi],     s1v[j], s2v[j]));
                    float v1 = fmaf(alpha[mi + 1], ay, fmaf(betaM[mi + 1], s1v[j], s2v[j]));
                    int ml = ty * 8 + mi;
                    so[(nl0 + j) * 256 + ml]     = v0;
                    so[(nl0 + j) * 256 + ml + 1] = v1;
                }
            }
        }
        __syncthreads();
#pragma unroll
        for (int r = 0; r < 16; r++) {
            int n = n0 + c * 16 + r;
            int m = m0 + tid;
            int b = m >> 14;
            int sp = m & 16383;
            out[(size_t)(b * 192 + n) * 16384 + sp] = so[r * 256 + tid];
        }
    }
}

// ---------------- launch ----------------
extern "C" void kernel_launch(void* const* d_in, const int* in_sizes, int n_in,
                              void* d_out, int out_size) {
    const float* x     = (const float*)d_in[0];  // (2,96,32,64,64)
    const float* gamma = (const float*)d_in[1];  // (768,)
    const float* beta  = (const float*)d_in[2];  // (768,)
    const float* w_red = (const float*)d_in[3];  // (768,192)
    float* out = (float*)d_out;                  // (2,192,16,32,32)

    k_scatter<<<49152, 256>>>(x);
    k_stats<<<512, 256>>>();
    k_wg<<<(768 * 192 + 255) / 256, 256>>>(gamma, w_red);
    k_s12<<<192, 256>>>(gamma, beta, w_red);
    dim3 grid(128, 3);
    k_gemm<<<grid, 256>>>(out);
}

// round 2
// speedup vs baseline: 1.2095x; 1.2095x over previous
#include <cuda_runtime.h>
#include <cstdint>

// ---------------- scratch (device globals) ----------------
__device__ float g_s1[192];             // sum_k gamma[k]*W[k][n]
__device__ float g_s2[192];             // sum_k beta[k]*W[k][n]

// ---------------- kernel 1: s1[n], s2[n] ----------------
__global__ void k_s12(const float* __restrict__ gamma, const float* __restrict__ beta,
                      const float* __restrict__ w) {
    int n = blockIdx.x;
    __shared__ float s1s[256];
    __shared__ float s2s[256];
    float s1 = 0.f, s2 = 0.f;
    for (int k = threadIdx.x; k < 768; k += 256) {
        float wv = w[k * 192 + n];
        s1 += gamma[k] * wv;
        s2 += beta[k] * wv;
    }
    s1s[threadIdx.x] = s1;
    s2s[threadIdx.x] = s2;
    __syncthreads();
    for (int off = 128; off > 0; off >>= 1) {
        if (threadIdx.x < off) {
            s1s[threadIdx.x] += s1s[threadIdx.x + off];
            s2s[threadIdx.x] += s2s[threadIdx.x + off];
        }
        __syncthreads();
    }
    if (threadIdx.x == 0) { g_s1[n] = s1s[0]; g_s2[n] = s2s[0]; }
}

// ---------------- fused gather + stats + GEMM + LN epilogue ----------------
__device__ __forceinline__ unsigned long long ffma2(unsigned long long a,
                                                    unsigned long long b,
                                                    unsigned long long c) {
    unsigned long long d;
    asm("fma.rn.f32x2 %0, %1, %2, %3;" : "=l"(d) : "l"(a), "l"(b), "l"(c));
    return d;
}

// Tile: 256 M x 64 N, KT=16, 256 threads, micro-tile 8M x 8N (f32x2-packed along M).
// A gathered straight from x (2,96,32,64,64); k = octant*96 + c;
// pos m = b*16384 + d*1024 + h*32 + w  (out spatial 16x32x32).
__global__ void __launch_bounds__(256, 2) k_gemm(const float* __restrict__ x,
                                                 const float* __restrict__ gamma,
                                                 const float* __restrict__ w_red,
                                                 float* __restrict__ out) {
    __shared__ float  As[2][16][256];   // 32 KB
    __shared__ float2 Bs[2][16][64];    // 16 KB (value duplicated, permuted)
    __shared__ float  sStat[512];       // rstd | -rstd*mu per local m

    const int m0  = blockIdx.x * 256;
    const int n0  = blockIdx.y * 64;
    const int tid = threadIdx.x;
    const int tx  = tid & 7;    // n-group
    const int ty  = tid >> 3;   // m-group

    // decode block's spatial coords
    const int b  = m0 >> 14;
    const int d  = (m0 >> 10) & 15;
    const int h0 = (m0 >> 5) & 31;

    // A-loader mapping: thread -> column m = m0 + tid  for all 16 k-rows
    const int hl = tid >> 5;    // 0..7
    const int wo = tid & 31;    // 0..31

    // B-loader mapping
    const int bRow  = tid >> 6;           // 0..3 (stride 4 -> 16 rows)
    const int bCol  = tid & 63;
    const int bPerm = ((bCol & 7) << 3) | (bCol >> 3);

    unsigned long long acc[4][8];
#pragma unroll
    for (int pi = 0; pi < 4; pi++)
#pragma unroll
        for (int j = 0; j < 8; j++) acc[pi][j] = 0ULL;

    float sA = 0.f, sQ = 0.f;   // per-thread LN stats for m = m0 + tid

    float aPf[16];
    float bPf[4];

    // ---- prefetch tile 0 ----
    {
        const int p = 0, c0 = 0;
        const int dz = (p >> 2) & 1, hy = (p >> 1) & 1, wx = p & 1;
        const float* abase = x + (((size_t)(b * 96 + c0) * 32 + 2 * d + dz) * 64
                                  + (2 * (h0 + hl) + hy)) * 64 + 2 * wo + wx;
#pragma unroll
        for (int r = 0; r < 16; r++) aPf[r] = abase[(size_t)r * 131072];
#pragma unroll
        for (int r = 0; r < 4; r++) {
            int k = bRow + r * 4;
            bPf[r] = gamma[k] * w_red[k * 192 + n0 + bCol];
        }
    }
#pragma unroll
    for (int r = 0; r < 16; r++) {
        As[0][r][tid] = aPf[r];
        sA += aPf[r];
        sQ = fmaf(aPf[r], aPf[r], sQ);
    }
#pragma unroll
    for (int r = 0; r < 4; r++)
        Bs[0][bRow + r * 4][bPerm] = make_float2(bPf[r], bPf[r]);
    __syncthreads();

    const int NT = 48;   // 768 / 16
    for (int t = 0; t < NT; t++) {
        int cur = t & 1;
        if (t < NT - 1) {
            int tt = t + 1;
            int k0 = tt * 16;
            int p  = tt / 6;
            int c0 = (tt - p * 6) * 16;
            int dz = (p >> 2) & 1, hy = (p >> 1) & 1, wx = p & 1;
            const float* abase = x + (((size_t)(b * 96 + c0) * 32 + 2 * d + dz) * 64
                                      + (2 * (h0 + hl) + hy)) * 64 + 2 * wo + wx;
#pragma unroll
            for (int r = 0; r < 16; r++) aPf[r] = abase[(size_t)r * 131072];
#pragma unroll
            for (int r = 0; r < 4; r++) {
                int k = k0 + bRow + r * 4;
                bPf[r] = gamma[k] * w_red[k * 192 + n0 + bCol];
            }
        }
#pragma unroll
        for (int kk = 0; kk < 16; kk++) {
            unsigned long long a2[4], b2[8];
#pragma unroll
            for (int pi = 0; pi < 4; pi++)
                a2[pi] = *reinterpret_cast<const unsigned long long*>(&As[cur][kk][ty * 8 + pi * 2]);
#pragma unroll
            for (int j = 0; j < 8; j++)
                b2[j] = *reinterpret_cast<const unsigned long long*>(&Bs[cur][kk][j * 8 + tx]);
#pragma unroll
            for (int pi = 0; pi < 4; pi++)
#pragma unroll
                for (int j = 0; j < 8; j++)
                    acc[pi][j] = ffma2(a2[pi], b2[j], acc[pi][j]);
        }
        if (t < NT - 1) {
            __syncthreads();
            int nxt = cur ^ 1;
#pragma unroll
            for (int r = 0; r < 16; r++) {
                As[nxt][r][tid] = aPf[r];
                sA += aPf[r];
                sQ = fmaf(aPf[r], aPf[r], sQ);
            }
#pragma unroll
            for (int r = 0; r < 4; r++)
                Bs[nxt][bRow + r * 4][bPerm] = make_float2(bPf[r], bPf[r]);
            __syncthreads();
        }
    }

    // ---- per-thread LayerNorm stats for m = m0 + tid ----
    {
        float mu  = sA * (1.0f / 768.0f);
        float var = sQ * (1.0f / 768.0f) - mu * mu;
        float rs  = rsqrtf(var + 1e-5f);
        sStat[tid]       = rs;
        sStat[256 + tid] = -rs * mu;
    }
    __syncthreads();

    // out = rstd*dot + (-rstd*mu)*s1[n] + s2[n]
    float alpha[8], betaM[8], s1v[8], s2v[8];
#pragma unroll
    for (int i = 0; i < 8; i++) {
        alpha[i] = sStat[ty * 8 + i];
        betaM[i] = sStat[256 + ty * 8 + i];
    }
#pragma unroll
    for (int j = 0; j < 8; j++) {
        int n = n0 + tx * 8 + j;
        s1v[j] = g_s1[n];
        s2v[j] = g_s2[n];
    }

    // stage through smem for coalesced channel-major writeback (4 chunks of 16 n)
    float* so = &As[0][0][0];   // reuse 16*256 floats
    for (int c = 0; c < 4; c++) {
        __syncthreads();
        if ((tx >> 1) == c) {
            int nl0 = (tx & 1) * 8;
#pragma unroll
            for (int pi = 0; pi < 4; pi++) {
#pragma unroll
                for (int j = 0; j < 8; j++) {
                    unsigned long long av = acc[pi][j];
                    float ax = __uint_as_float((unsigned)(av & 0xffffffffu));
                    float ay = __uint_as_float((unsigned)(av >> 32));
                    int mi = pi * 2;
                    float v0 = fmaf(alpha[mi],     ax, fmaf(betaM[mi],     s1v[j], s2v[j]));
                    float v1 = fmaf(alpha[mi + 1], ay, fmaf(betaM[mi + 1], s1v[j], s2v[j]));
                    int ml = ty * 8 + mi;
                    so[(nl0 + j) * 256 + ml]     = v0;
                    so[(nl0 + j) * 256 + ml + 1] = v1;
                }
            }
        }
        __syncthreads();
#pragma unroll
        for (int r = 0; r < 16; r++) {
            int n = n0 + c * 16 + r;
            int m = m0 + tid;
            int bb = m >> 14;
            int sp = m & 16383;
            out[(size_t)(bb * 192 + n) * 16384 + sp] = so[r * 256 + tid];
        }
    }
}

// ---------------- launch ----------------
extern "C" void kernel_launch(void* const* d_in, const int* in_sizes, int n_in,
                              void* d_out, int out_size) {
    const float* x     = (const float*)d_in[0];  // (2,96,32,64,64)
    const float* gamma = (const float*)d_in[1];  // (768,)
    const float* beta  = (const float*)d_in[2];  // (768,)
    const float* w_red = (const float*)d_in[3];  // (768,192)
    float* out = (float*)d_out;                  // (2,192,16,32,32)

    k_s12<<<192, 256>>>(gamma, beta, w_red);
    dim3 grid(128, 3);
    k_gemm<<<grid, 256>>>(x, gamma, w_red, out);
}

// round 4
// speedup vs baseline: 2.8607x; 2.3652x over previous
#include <cuda_runtime.h>
#include <cuda_bf16.h>
#include <cstdint>

// ============================================================================
// helpers
// ============================================================================
__device__ __forceinline__ uint32_t smem_u32(const void* p) {
    uint32_t a;
    asm("{ .reg .u64 t; cvta.to.shared.u64 t, %1; cvt.u32.u64 %0, t; }" : "=r"(a) : "l"(p));
    return a;
}
__host__ __device__ __forceinline__ uint32_t swz128(uint32_t off) {
    return off ^ ((off >> 3) & 0x70);
}
__device__ __forceinline__ void ldsm4(uint32_t r[4], uint32_t addr) {
    asm volatile("ldmatrix.sync.aligned.m8n8.x4.shared.b16 {%0,%1,%2,%3}, [%4];"
                 : "=r"(r[0]), "=r"(r[1]), "=r"(r[2]), "=r"(r[3]) : "r"(addr));
}
__device__ __forceinline__ void mma16816(float d[4], const uint32_t a[4], uint32_t b0, uint32_t b1) {
    asm volatile("mma.sync.aligned.m16n8k16.row.col.f32.bf16.bf16.f32 "
                 "{%0,%1,%2,%3}, {%4,%5,%6,%7}, {%8,%9}, {%0,%1,%2,%3};"
                 : "+f"(d[0]), "+f"(d[1]), "+f"(d[2]), "+f"(d[3])
                 : "r"(a[0]), "r"(a[1]), "r"(a[2]), "r"(a[3]), "r"(b0), "r"(b1));
}

// ============================================================================
// layout constants
// ============================================================================
// A tile: 128 m x 64 k̂ bf16 (hi & lo), 128B swizzled rows.
// B tile: 192 n x 64 k̂ bf16 (hi & lo), 128B swizzled rows, pre-swizzled in gmem.
static constexpr int SMEM_AHI = 0;        // 16 KB
static constexpr int SMEM_ALO = 16384;    // 16 KB
static constexpr int SMEM_BHI = 32768;    // 24 KB
static constexpr int SMEM_BLO = 57344;    // 24 KB
static constexpr int SMEM_MISC = 81920;   // s1[192] | s2[192] | stat[256]
static constexpr int OFF_S1   = SMEM_MISC;
static constexpr int OFF_S2   = SMEM_MISC + 768;
static constexpr int OFF_STAT = SMEM_MISC + 1536;
static constexpr int SMEM_TOTAL = SMEM_MISC + 1536 + 1024;   // 84480
// epilogue scratch (overlaps A/B regions, used after compute)
static constexpr int OFF_PSUM = 49152;
static constexpr int OFF_PSQ  = 53248;

// ---------------- device scratch ----------------
__device__ float g_s1[192];
__device__ float g_s2[192];
__device__ float4 g_B4[36864];   // 12 chunks x 48KB (hi 24KB + lo 24KB), pre-swizzled

// ---------------- kernel: s1/s2 ----------------
__global__ void k_s12(const float* __restrict__ gamma, const float* __restrict__ beta,
                      const float* __restrict__ w) {
    int n = blockIdx.x;
    __shared__ float s1s[256], s2s[256];
    float s1 = 0.f, s2 = 0.f;
    for (int k = threadIdx.x; k < 768; k += 256) {
        float wv = w[k * 192 + n];
        s1 += gamma[k] * wv;
        s2 += beta[k] * wv;
    }
    s1s[threadIdx.x] = s1; s2s[threadIdx.x] = s2;
    __syncthreads();
    for (int off = 128; off > 0; off >>= 1) {
        if (threadIdx.x < off) { s1s[threadIdx.x] += s1s[threadIdx.x + off]; s2s[threadIdx.x] += s2s[threadIdx.x + off]; }
        __syncthreads();
    }
    if (threadIdx.x == 0) { g_s1[n] = s1s[0]; g_s2[n] = s2s[0]; }
}

// ---------------- kernel: B precompute (gamma*W -> bf16 hi/lo, swizzled tile layout) --------
__global__ void k_bprep(const float* __restrict__ gamma, const float* __restrict__ w) {
    int t = blockIdx.x * 256 + threadIdx.x;
    if (t >= 768 * 192) return;
    int k = t / 192;       // original k = p*96 + c
    int n = t % 192;
    int p = k / 96, c = k % 96;
    float val = gamma[k] * w[k * 192 + n];
    __nv_bfloat16 hi = __float2bfloat16_rn(val);
    __nv_bfloat16 lo = __float2bfloat16_rn(val - __bfloat162float(hi));
    int chunk = c >> 3;
    int kl = (c & 7) * 8 + p;              // k̂ within chunk
    uint32_t off = swz128((uint32_t)(n * 128 + kl * 2));
    unsigned char* base = (unsigned char*)g_B4 + chunk * 49152;
    *(__nv_bfloat16*)(base + off)         = hi;
    *(__nv_bfloat16*)(base + 24576 + off) = lo;
}

// ---------------- main fused kernel ----------------
__global__ void __launch_bounds__(256, 2) k_main(const float* __restrict__ x,
                                                 float* __restrict__ out) {
    extern __shared__ unsigned char smem[];
    const uint32_t sb  = smem_u32(smem);
    const int tid  = threadIdx.x;
    const int lane = tid & 31;
    const int wrp  = tid >> 5;
    const int wm   = wrp & 3;       // M quadrant (32 rows each)
    const int wn   = wrp >> 2;      // N half (96 cols each)

    if (tid < 192) {
        ((float*)(smem + OFF_S1))[tid] = g_s1[tid];
        ((float*)(smem + OFF_S2))[tid] = g_s2[tid];
    }

    // block coords: 128 consecutive m
    const int m0 = blockIdx.x * 128;
    const int b  = m0 >> 14;
    const int d  = (m0 >> 10) & 15;
    const int h0 = (m0 >> 5) & 31;     // multiple of 4
    const int idx = tid >> 5;          // c_local 0..7 (loader role)
    const int w   = tid & 31;

    const float2* x2 = (const float2*)x;
    const size_t baseIdx = ((size_t)(b * 96 + idx) * 32 + 2 * d) * 2048 + (size_t)(2 * h0) * 32 + w;

    // ldmatrix lane address components
    const int g  = lane >> 3, rl = lane & 7;
    const int aRowLane = ((g & 1) << 3) + rl;
    const int aKLane   = (g >> 1) << 4;
    const int bRowLane = ((g >> 1) << 3) + rl;
    const int bKLane   = (g & 1) << 4;

    float acc[2][12][4];
#pragma unroll
    for (int mt = 0; mt < 2; mt++)
#pragma unroll
        for (int ng = 0; ng < 12; ng++)
#pragma unroll
            for (int r = 0; r < 4; r++) acc[mt][ng][r] = 0.f;

    float sA[4] = {0.f, 0.f, 0.f, 0.f};
    float sQ[4] = {0.f, 0.f, 0.f, 0.f};

    float4* B4s = (float4*)(smem + SMEM_BHI);

    for (int t = 0; t < 12; t++) {
        if (t) __syncthreads();   // previous compute done; smem reusable

        // ---- B copy (pre-swizzled, hi+lo = 48KB) ----
#pragma unroll
        for (int j = 0; j < 12; j++)
            B4s[j * 256 + tid] = g_B4[(size_t)t * 3072 + j * 256 + tid];

        // ---- A gather + convert + stats + STS ----
        const size_t cb = baseIdx + (size_t)t * 524288;
#pragma unroll
        for (int i = 0; i < 16; i++) {
            float2 v = x2[cb + (size_t)((i >> 3) * 2048 + ((i >> 1) & 3) * 64 + (i & 1) * 32)];
            const int dz = i >> 3, hout = (i >> 1) & 3, hy = i & 1;
            const int kl = idx * 8 + dz * 4 + hy * 2;
            const int ml = hout * 32 + w;
            __nv_bfloat162 hi2 = __float22bfloat162_rn(v);
            float2 hf = __bfloat1622float2(hi2);
            __nv_bfloat162 lo2 = __float22bfloat162_rn(make_float2(v.x - hf.x, v.y - hf.y));
            uint32_t off = swz128((uint32_t)(ml * 128 + kl * 2));
            *(uint32_t*)(smem + SMEM_AHI + off) = *(uint32_t*)&hi2;
            *(uint32_t*)(smem + SMEM_ALO + off) = *(uint32_t*)&lo2;
            sA[hout] += v.x + v.y;
            sQ[hout] = fmaf(v.x, v.x, fmaf(v.y, v.y, sQ[hout]));
        }
        __syncthreads();

        // ---- compute: 4 k16-steps x 3 terms ----
#pragma unroll
        for (int ks = 0; ks < 4; ks++) {
            uint32_t ahi[2][4], alo[2][4];
#pragma unroll
            for (int mt = 0; mt < 2; mt++) {
                uint32_t rowoff = (uint32_t)((wm * 32 + mt * 16 + aRowLane) * 128 + ks * 32 + aKLane);
                ldsm4(ahi[mt], sb + SMEM_AHI + swz128(rowoff));
                ldsm4(alo[mt], sb + SMEM_ALO + swz128(rowoff));
            }
#pragma unroll
            for (int ng2 = 0; ng2 < 6; ng2++) {
                uint32_t boff = (uint32_t)((wn * 96 + ng2 * 16 + bRowLane) * 128 + ks * 32 + bKLane);
                uint32_t bb[4];
                ldsm4(bb, sb + SMEM_BHI + swz128(boff));
                mma16816(acc[0][2 * ng2],     ahi[0], bb[0], bb[1]);
                mma16816(acc[1][2 * ng2],     ahi[1], bb[0], bb[1]);
                mma16816(acc[0][2 * ng2 + 1], ahi[0], bb[2], bb[3]);
                mma16816(acc[1][2 * ng2 + 1], ahi[1], bb[2], bb[3]);
                mma16816(acc[0][2 * ng2],     alo[0], bb[0], bb[1]);
                mma16816(acc[1][2 * ng2],     alo[1], bb[0], bb[1]);
                mma16816(acc[0][2 * ng2 + 1], alo[0], bb[2], bb[3]);
                mma16816(acc[1][2 * ng2 + 1], alo[1], bb[2], bb[3]);
            }
#pragma unroll
            for (int ng2 = 0; ng2 < 6; ng2++) {
                uint32_t boff = (uint32_t)((wn * 96 + ng2 * 16 + bRowLane) * 128 + ks * 32 + bKLane);
                uint32_t bb[4];
                ldsm4(bb, sb + SMEM_BLO + swz128(boff));
                mma16816(acc[0][2 * ng2],     ahi[0], bb[0], bb[1]);
                mma16816(acc[1][2 * ng2],     ahi[1], bb[0], bb[1]);
                mma16816(acc[0][2 * ng2 + 1], ahi[0], bb[2], bb[3]);
                mma16816(acc[1][2 * ng2 + 1], ahi[1], bb[2], bb[3]);
            }
        }
    }
    __syncthreads();

    // ---- LayerNorm stats reduce ----
    float* psum = (float*)(smem + OFF_PSUM);
    float* psq  = (float*)(smem + OFF_PSQ);
#pragma unroll
    for (int hout = 0; hout < 4; hout++) {
        psum[idx * 128 + hout * 32 + w] = sA[hout];
        psq[idx * 128 + hout * 32 + w]  = sQ[hout];
    }
    __syncthreads();
    float* stat = (float*)(smem + OFF_STAT);
    if (tid < 128) {
        float S = 0.f, Q = 0.f;
#pragma unroll
        for (int r = 0; r < 8; r++) { S += psum[r * 128 + tid]; Q += psq[r * 128 + tid]; }
        float mu  = S * (1.0f / 768.0f);
        float var = Q * (1.0f / 768.0f) - mu * mu;
        float rs  = rsqrtf(var + 1e-5f);
        stat[tid]       = rs;
        stat[128 + tid] = -rs * mu;
    }
    __syncthreads();

    // ---- epilogue: LN affine + transposed writeback (two n-halves of 96) ----
    float* sbuf = (float*)smem;   // 96 x 128 floats = 48 KB
    const float* s1s = (const float*)(smem + OFF_S1);
    const float* s2s = (const float*)(smem + OFF_S2);
    const int sp0 = (m0 & 16383);
    for (int h = 0; h < 2; h++) {
        if (wn == h) {
#pragma unroll
            for (int mt = 0; mt < 2; mt++)
#pragma unroll
                for (int ng = 0; ng < 12; ng++)
#pragma unroll
                    for (int r = 0; r < 4; r++) {
                        int m_loc = wm * 32 + mt * 16 + (lane >> 2) + ((r >> 1) << 3);
                        int n_loc = ng * 8 + ((lane & 3) << 1) + (r & 1);
                        int n_glb = h * 96 + n_loc;
                        float v = fmaf(stat[m_loc], acc[mt][ng][r],
                                       fmaf(stat[128 + m_loc], s1s[n_glb], s2s[n_glb]));
                        sbuf[n_loc * 128 + m_loc] = v;
                    }
        }
        __syncthreads();
#pragma unroll
        for (int r = 0; r < 48; r++) {
            int e  = r * 256 + tid;
            int nl = e >> 7;
            int ml = e & 127;
            int n  = h * 96 + nl;
            out[(size_t)(b * 192 + n) * 16384 + sp0 + ml] = sbuf[e];
        }
        if (h == 0) __syncthreads();
    }
}

// ---------------- launch ----------------
extern "C" void kernel_launch(void* const* d_in, const int* in_sizes, int n_in,
                              void* d_out, int out_size) {
    const float* x     = (const float*)d_in[0];
    const float* gamma = (const float*)d_in[1];
    const float* beta  = (const float*)d_in[2];
    const float* w_red = (const float*)d_in[3];
    float* out = (float*)d_out;

    cudaFuncSetAttribute(k_main, cudaFuncAttributeMaxDynamicSharedMemorySize, SMEM_TOTAL);

    k_s12<<<192, 256>>>(gamma, beta, w_red);
    k_bprep<<<576, 256>>>(gamma, w_red);
    k_main<<<256, 256, SMEM_TOTAL>>>(x, out);
}